// round 11
// baseline (speedup 1.0000x reference)
#include <cuda_runtime.h>
#include <cstdint>
#include <math.h>

// Problem constants
#define NB   64
#define SEQL 512
#define DIN  256
#define NF   256
#define KSZ  3
#define NJ   768                 // KSZ*NF

// Static device scratch (no allocs allowed)
__device__ float g_Vr [NJ * DIN];              // rna(V)^T   [j][e]
__device__ float g_Bwt[NJ * DIN];              // Bw^T       [j][d]
__device__ float g_Ub [NB * DIN * DIN];        // rna(U * sig_b)  [b][d][e]
__device__ float g_Wt [NB * NF * NJ];          // weights    [b][f][kd] (kd = k*256+d)

// ---------------------------------------------------------------------------
// Helpers
// ---------------------------------------------------------------------------
__device__ __forceinline__ uint32_t smem_u32(const void* p) {
    uint32_t a;
    asm("{ .reg .u64 t; cvta.to.shared.u64 t, %1; cvt.u32.u64 %0, t; }"
        : "=r"(a) : "l"(p));
    return a;
}
__device__ __forceinline__ float rna(float x) {
    uint32_t u;
    asm("cvt.rna.tf32.f32 %0, %1;" : "=r"(u) : "f"(x));
    return __uint_as_float(u);
}
__device__ __forceinline__ uint32_t rna_u(uint32_t x) {
    uint32_t u;
    asm("cvt.rna.tf32.f32 %0, %1;" : "=r"(u) : "r"(x));
    return u;
}
#define CP16(dst, src) \
    asm volatile("cp.async.cg.shared.global [%0], [%1], 16;" :: "r"(dst), "l"(src))
#define CP16Z(dst, src, sz) \
    asm volatile("cp.async.cg.shared.global [%0], [%1], 16, %2;" :: "r"(dst), "l"(src), "r"(sz))
#define CP_COMMIT() asm volatile("cp.async.commit_group;")
#define CP_WAIT1()  asm volatile("cp.async.wait_group 1;" ::: "memory")
#define CP_WAIT0()  asm volatile("cp.async.wait_group 0;" ::: "memory")

#define LDM4(r0, r1, r2, r3, addr) \
    asm volatile("ldmatrix.sync.aligned.m8n8.x4.shared.b16 {%0,%1,%2,%3}, [%4];" \
        : "=r"(r0), "=r"(r1), "=r"(r2), "=r"(r3) : "r"(addr))

// ---------------------------------------------------------------------------
// SMEM stage (32 KB; three stages = 96 KB dynamic):
//   As: 128 rows (M) x 32 floats (K), 128 B/row; 16B chunk c (0..7) of row r
//       at r*128 + ((c ^ (r&7))<<4)                          [16384 B]
//   Bs: 128 rows (N) x 32 floats (K), same layout/swizzle    [16384 B]
// ---------------------------------------------------------------------------
#define STAGE_BYTES 32768
#define NSTAGE      3
#define SMEM_BYTES  (STAGE_BYTES * NSTAGE)

// One BK=32 slab: warp tile 32(M) x 64(N), m16n8k8 tf32, acc[64].
// RNA_A: round A fragments to tf32 in-register (A tile holds raw fp32).
template <bool RNA_A>
__device__ __forceinline__ void tile_mma(float* __restrict__ acc,
                                         uint32_t Aa, uint32_t Ba,
                                         int lane, int wm, int wn)
{
    const uint32_t s     = lane & 7;
    const uint32_t ahalf = (lane >> 4) & 1;        // A: chunk parity
    const uint32_t bhalf = (lane >> 3) & 1;        // B: chunk parity
    const uint32_t abase = Aa + (wm * 32 + (lane & 15)) * 128;
    const uint32_t bbase = Ba + (wn * 64 + ((lane >> 4) & 1) * 8 + (lane & 7)) * 128;

    #pragma unroll
    for (int ks = 0; ks < 4; ++ks) {
        const uint32_t ca = ((2 * ks + ahalf) ^ s) << 4;
        const uint32_t cb = ((2 * ks + bhalf) ^ s) << 4;

        uint32_t a0[4], a1[4];
        LDM4(a0[0], a0[1], a0[2], a0[3], abase + ca);           // rows m..m+15
        LDM4(a1[0], a1[1], a1[2], a1[3], abase + 2048 + ca);    // +16 rows
        if (RNA_A) {
            #pragma unroll
            for (int i = 0; i < 4; ++i) { a0[i] = rna_u(a0[i]); a1[i] = rna_u(a1[i]); }
        }

        uint32_t bf[4][4];
        #pragma unroll
        for (int q = 0; q < 4; ++q)
            LDM4(bf[q][0], bf[q][1], bf[q][2], bf[q][3], bbase + q * 2048 + cb);

        #pragma unroll
        for (int q = 0; q < 4; ++q)
            #pragma unroll
            for (int p = 0; p < 2; ++p) {
                const int ni = 2 * q + p;
                const uint32_t b0 = bf[q][2 * p], b1 = bf[q][2 * p + 1];
                {
                    float* c = &acc[ni * 4];
                    asm volatile(
                        "mma.sync.aligned.m16n8k8.row.col.f32.tf32.tf32.f32 "
                        "{%0,%1,%2,%3}, {%4,%5,%6,%7}, {%8,%9}, {%0,%1,%2,%3};"
                        : "+f"(c[0]), "+f"(c[1]), "+f"(c[2]), "+f"(c[3])
                        : "r"(a0[0]), "r"(a0[1]), "r"(a0[2]), "r"(a0[3]),
                          "r"(b0), "r"(b1));
                }
                {
                    float* c = &acc[(8 + ni) * 4];
                    asm volatile(
                        "mma.sync.aligned.m16n8k8.row.col.f32.tf32.tf32.f32 "
                        "{%0,%1,%2,%3}, {%4,%5,%6,%7}, {%8,%9}, {%0,%1,%2,%3};"
                        : "+f"(c[0]), "+f"(c[1]), "+f"(c[2]), "+f"(c[3])
                        : "r"(a1[0]), "r"(a1[1]), "r"(a1[2]), "r"(a1[3]),
                          "r"(b0), "r"(b1));
                }
            }
    }
}

// ---------------------------------------------------------------------------
// Prep A: tiled transposes. z==0: g_Vr[j][e] = rna(V[e][j]);
//                           z==1: g_Bwt[j][d] = Bw[d][j]
//   grid (NJ/32, DIN/32, 2), block (32, 8)
// ---------------------------------------------------------------------------
__global__ void prep_tr(const float* __restrict__ V,
                        const float* __restrict__ Bw)
{
    __shared__ float tile[32][33];
    const int j0 = blockIdx.x * 32, e0 = blockIdx.y * 32;
    const int tx = threadIdx.x, ty = threadIdx.y;
    const bool isV = (blockIdx.z == 0);
    const float* src = isV ? V : Bw;
    float* dst = isV ? g_Vr : g_Bwt;

    #pragma unroll
    for (int i = 0; i < 4; ++i) {
        const int r = ty + i * 8;
        float v = src[(size_t)(e0 + r) * NJ + j0 + tx];
        if (isV) v = rna(v);
        tile[r][tx] = v;
    }
    __syncthreads();
    #pragma unroll
    for (int i = 0; i < 4; ++i) {
        const int r = ty + i * 8;
        dst[(size_t)(j0 + r) * DIN + e0 + tx] = tile[tx][r];
    }
}

// ---------------------------------------------------------------------------
// Prep B: g_Ub[b][d][e] = rna(U[d][e] * sigmoid(z[b][e]))
// ---------------------------------------------------------------------------
__global__ void prep2(const float* __restrict__ U, const float* __restrict__ z)
{
    const int b = blockIdx.x, dblk = blockIdx.y;
    const int t = threadIdx.x;
    const int d  = dblk * 4 + (t >> 6);
    const int e4 = (t & 63) * 4;
    const float4 u  = *(const float4*)(U + (size_t)d * DIN + e4);
    const float4 zv = *(const float4*)(z + (size_t)b * DIN + e4);
    float4 o;
    o.x = rna(u.x / (1.f + expf(-zv.x)));
    o.y = rna(u.y / (1.f + expf(-zv.y)));
    o.z = rna(u.z / (1.f + expf(-zv.z)));
    o.w = rna(u.w / (1.f + expf(-zv.w)));
    *(float4*)(g_Ub + ((size_t)(b * DIN + d)) * DIN + e4) = o;
}

// ---------------------------------------------------------------------------
// GEMM1 (roles swapped): per b: D[j][d] = sum_e Vr[j][e] * Ub[b][d][e]
//   M = j (6 tiles of 128 over 768), N = d (2 tiles of 128 over 256), K=256
//   epilogue: + Bwt[j][d], rna, store g_Wt[b][f][kq*256+d]  — coalesced in d
// ---------------------------------------------------------------------------
__global__ __launch_bounds__(256, 2)
void gemm_w()
{
    extern __shared__ char sm[];
    const int b = blockIdx.z, m0 = blockIdx.x * 128, n0 = blockIdx.y * 128;
    const int kq = m0 >> 8, f0 = m0 & 255;
    const int tid = (int)threadIdx.x, wid = tid >> 5, lane = tid & 31;
    const int gid = lane >> 2, tig = lane & 3, wm = wid & 3, wn = wid >> 2;

    const uint32_t sb = smem_u32(sm);
    const float* Asrc = g_Vr + (size_t)m0 * DIN;                       // [j][e]
    const float* Bsrc = g_Ub + (size_t)b * DIN * DIN + (size_t)n0 * DIN; // [d][e]

    float acc[64];
    #pragma unroll
    for (int i = 0; i < 64; ++i) acc[i] = 0.f;

    auto load = [&](int t) {
        const int e0 = t * 32, st = t % NSTAGE;
        const uint32_t ab = sb + st * STAGE_BYTES;
        const uint32_t bb = ab + 16384;
        #pragma unroll
        for (int i = 0; i < 4; ++i) {
            const int c = tid + i * 256;
            const int r = c >> 3, c4 = c & 7;
            CP16(ab + r * 128 + ((c4 ^ (r & 7)) << 4),
                 Asrc + (size_t)r * DIN + e0 + c4 * 4);
        }
        #pragma unroll
        for (int i = 0; i < 4; ++i) {
            const int c = tid + i * 256;
            const int r = c >> 3, c4 = c & 7;
            CP16(bb + r * 128 + ((c4 ^ (r & 7)) << 4),
                 Bsrc + (size_t)r * DIN + e0 + c4 * 4);
        }
        CP_COMMIT();
    };

    load(0); load(1);
    for (int t = 0; t < 8; ++t) {
        if (t < 7) CP_WAIT1(); else CP_WAIT0();
        __syncthreads();
        if (t + 2 < 8) load(t + 2);
        const uint32_t stg = sb + (t % NSTAGE) * STAGE_BYTES;
        tile_mma<false>(acc, stg, stg + 16384, lane, wm, wn);
    }

    // epilogue: + Bwt, rna, store g_Wt[b][f][kq*256+d] (contiguous in d)
    #pragma unroll
    for (int mi = 0; mi < 2; ++mi)
        #pragma unroll
        for (int h = 0; h < 2; ++h) {
            const int jl = wm * 32 + mi * 16 + gid + 8 * h;   // j within tile
            const int f  = f0 + jl;
            const float* BwRow = g_Bwt + (size_t)(m0 + jl) * DIN + n0;
            float* Wrow = g_Wt + (size_t)b * NF * NJ + (size_t)f * NJ
                        + (size_t)kq * DIN + n0;
            #pragma unroll
            for (int ni = 0; ni < 8; ++ni) {
                const int dl = wn * 64 + ni * 8 + 2 * tig;
                const float2 bw = *(const float2*)(BwRow + dl);
                const float* c = &acc[(mi * 8 + ni) * 4 + 2 * h];
                float2 w;
                w.x = rna(c[0] + bw.x);
                w.y = rna(c[1] + bw.y);
                *(float2*)(Wrow + dl) = w;
            }
        }
}

// ---------------------------------------------------------------------------
// Conv: per b: out[l][f] = relu( sum_{kd<768} A[l][kd] * Wt[b][f][kd] + bias )
//   A[l][kd] = x[b] flat at (l-1)*256 + kd, zero outside [0, 512*256)
//   A is raw fp32; fragments rounded to tf32 in-register (RNA_A).
//   CTA 128x128, 256 thr (8 warps, 4x2 of 32x64), BK=32, K=768 (24 tiles)
// ---------------------------------------------------------------------------
__global__ __launch_bounds__(256, 2)
void conv_mma(const float* __restrict__ x,
              const float* __restrict__ bias, float* __restrict__ out)
{
    extern __shared__ char sm[];
    const int b = blockIdx.z, l0 = blockIdx.y * 128, f0 = blockIdx.x * 128;
    const int tid = (int)threadIdx.x, wid = tid >> 5, lane = tid & 31;
    const int gid = lane >> 2, tig = lane & 3, wm = wid & 3, wn = wid >> 2;

    const uint32_t sb = smem_u32(sm);
    const float* xb = x + (size_t)b * SEQL * DIN;
    const float* Wsrc = g_Wt + ((size_t)b * NF + f0) * NJ;

    float acc[64];
    #pragma unroll
    for (int i = 0; i < 64; ++i) acc[i] = 0.f;

    auto load = [&](int t) {
        const int e0 = t * 32, st = t % NSTAGE;
        const uint32_t ab = sb + st * STAGE_BYTES;
        const uint32_t bb = ab + 16384;
        #pragma unroll
        for (int i = 0; i < 4; ++i) {
            const int c = tid + i * 256;
            const int r = c >> 3, c4 = c & 7;
            const int idx = (l0 + r - 1) * DIN + e0 + c4 * 4;
            const unsigned ok = ((unsigned)idx < (unsigned)(SEQL * DIN));
            const float* src = xb + (ok ? idx : 0);
            CP16Z(ab + r * 128 + ((c4 ^ (r & 7)) << 4), src, ok ? 16u : 0u);
        }
        #pragma unroll
        for (int i = 0; i < 4; ++i) {
            const int c = tid + i * 256;
            const int r = c >> 3, c4 = c & 7;
            CP16(bb + r * 128 + ((c4 ^ (r & 7)) << 4),
                 Wsrc + (size_t)r * NJ + e0 + c4 * 4);
        }
        CP_COMMIT();
    };

    load(0); load(1);
    for (int t = 0; t < 24; ++t) {
        if (t < 23) CP_WAIT1(); else CP_WAIT0();
        __syncthreads();
        if (t + 2 < 24) load(t + 2);
        const uint32_t stg = sb + (t % NSTAGE) * STAGE_BYTES;
        tile_mma<true>(acc, stg, stg + 16384, lane, wm, wn);
    }

    // epilogue: + bias, relu, store (f contiguous)
    #pragma unroll
    for (int mi = 0; mi < 2; ++mi)
        #pragma unroll
        for (int h = 0; h < 2; ++h) {
            const int l = l0 + wm * 32 + mi * 16 + gid + 8 * h;
            float* Orow = out + ((size_t)b * SEQL + l) * NF + f0;
            #pragma unroll
            for (int ni = 0; ni < 8; ++ni) {
                const int fl = wn * 64 + ni * 8 + 2 * tig;
                const float2 bv = *(const float2*)(bias + f0 + fl);
                const float* c = &acc[(mi * 8 + ni) * 4 + 2 * h];
                float2 o;
                o.x = fmaxf(c[0] + bv.x, 0.f);
                o.y = fmaxf(c[1] + bv.y, 0.f);
                *(float2*)(Orow + fl) = o;
            }
        }
}

// ---------------------------------------------------------------------------
// kernel_launch: prep_tr -> prep2 -> gemm_w -> conv (capturable, no allocs)
// Inputs: x, z, U, V, B_w, b, kernel_size(ignored; KSZ=3)
// ---------------------------------------------------------------------------
extern "C" void kernel_launch(void* const* d_in, const int* in_sizes, int n_in,
                              void* d_out, int out_size)
{
    (void)in_sizes; (void)n_in; (void)out_size;
    const float* x    = (const float*)d_in[0];
    const float* z    = (const float*)d_in[1];
    const float* U    = (const float*)d_in[2];
    const float* V    = (const float*)d_in[3];
    const float* Bw   = (const float*)d_in[4];
    const float* bias = (const float*)d_in[5];
    float* out = (float*)d_out;

    static bool attr_done = false;
    if (!attr_done) {
        cudaFuncSetAttribute(gemm_w,   cudaFuncAttributeMaxDynamicSharedMemorySize, SMEM_BYTES);
        cudaFuncSetAttribute(conv_mma, cudaFuncAttributeMaxDynamicSharedMemorySize, SMEM_BYTES);
        attr_done = true;
    }

    prep_tr<<<dim3(NJ / 32, DIN / 32, 2), dim3(32, 8)>>>(V, Bw);
    prep2<<<dim3(NB, DIN / 4), 256>>>(U, z);
    gemm_w<<<dim3(NJ / 128, DIN / 128, NB), 256, SMEM_BYTES>>>();
    conv_mma<<<dim3(NF / 128, SEQL / 128, NB), 256, SMEM_BYTES>>>(x, bias, out);
}

// round 12
// speedup vs baseline: 1.0278x; 1.0278x over previous
#include <cuda_runtime.h>
#include <cstdint>
#include <math.h>

// Problem constants
#define NB   64
#define SEQL 512
#define DIN  256
#define NF   256
#define KSZ  3
#define NJ   768                 // KSZ*NF

// Static device scratch (no allocs allowed)
__device__ float g_Vr [NJ * DIN];              // rna(V)^T   [j][e]
__device__ float g_Bwt[NJ * DIN];              // Bw^T       [j][d]
__device__ float g_Ub [NB * DIN * DIN];        // rna(U * sig_b)  [b][d][e]
__device__ float g_Wt [NB * NF * NJ];          // weights    [b][f][kd] (kd = k*256+d)

// ---------------------------------------------------------------------------
// Helpers
// ---------------------------------------------------------------------------
__device__ __forceinline__ uint32_t smem_u32(const void* p) {
    uint32_t a;
    asm("{ .reg .u64 t; cvta.to.shared.u64 t, %1; cvt.u32.u64 %0, t; }"
        : "=r"(a) : "l"(p));
    return a;
}
__device__ __forceinline__ float rna(float x) {
    uint32_t u;
    asm("cvt.rna.tf32.f32 %0, %1;" : "=r"(u) : "f"(x));
    return __uint_as_float(u);
}
#define CP16(dst, src) \
    asm volatile("cp.async.cg.shared.global [%0], [%1], 16;" :: "r"(dst), "l"(src))
#define CP16Z(dst, src, sz) \
    asm volatile("cp.async.cg.shared.global [%0], [%1], 16, %2;" :: "r"(dst), "l"(src), "r"(sz))
#define CP_COMMIT() asm volatile("cp.async.commit_group;")
#define CP_WAIT1()  asm volatile("cp.async.wait_group 1;" ::: "memory")
#define CP_WAIT0()  asm volatile("cp.async.wait_group 0;" ::: "memory")

#define LDM4(r0, r1, r2, r3, addr) \
    asm volatile("ldmatrix.sync.aligned.m8n8.x4.shared.b16 {%0,%1,%2,%3}, [%4];" \
        : "=r"(r0), "=r"(r1), "=r"(r2), "=r"(r3) : "r"(addr))

// ---------------------------------------------------------------------------
// SMEM stage (32 KB; three stages = 96 KB dynamic):
//   As: 128 rows (M) x 32 floats (K), 128 B/row; 16B chunk c (0..7) of row r
//       at r*128 + ((c ^ (r&7))<<4)                          [16384 B]
//   Bs: 128 rows (N) x 32 floats (K), same layout/swizzle    [16384 B]
// ---------------------------------------------------------------------------
#define STAGE_BYTES 32768
#define NSTAGE      3
#define SMEM_BYTES  (STAGE_BYTES * NSTAGE)

// One BK=32 slab: warp tile 32(M) x 64(N), m16n8k8 tf32, acc[64].
// A operand may be raw fp32: HW mma truncates to tf32 (RZ) — no cvt needed.
__device__ __forceinline__ void tile_mma(float* __restrict__ acc,
                                         uint32_t Aa, uint32_t Ba,
                                         int lane, int wm, int wn)
{
    const uint32_t s     = lane & 7;
    const uint32_t ahalf = (lane >> 4) & 1;        // A: chunk parity
    const uint32_t bhalf = (lane >> 3) & 1;        // B: chunk parity
    const uint32_t abase = Aa + (wm * 32 + (lane & 15)) * 128;
    const uint32_t bbase = Ba + (wn * 64 + ((lane >> 4) & 1) * 8 + (lane & 7)) * 128;

    #pragma unroll
    for (int ks = 0; ks < 4; ++ks) {
        const uint32_t ca = ((2 * ks + ahalf) ^ s) << 4;
        const uint32_t cb = ((2 * ks + bhalf) ^ s) << 4;

        uint32_t a0[4], a1[4];
        LDM4(a0[0], a0[1], a0[2], a0[3], abase + ca);           // rows m..m+15
        LDM4(a1[0], a1[1], a1[2], a1[3], abase + 2048 + ca);    // +16 rows

        uint32_t bf[4][4];
        #pragma unroll
        for (int q = 0; q < 4; ++q)
            LDM4(bf[q][0], bf[q][1], bf[q][2], bf[q][3], bbase + q * 2048 + cb);

        #pragma unroll
        for (int q = 0; q < 4; ++q)
            #pragma unroll
            for (int p = 0; p < 2; ++p) {
                const int ni = 2 * q + p;
                const uint32_t b0 = bf[q][2 * p], b1 = bf[q][2 * p + 1];
                {
                    float* c = &acc[ni * 4];
                    asm volatile(
                        "mma.sync.aligned.m16n8k8.row.col.f32.tf32.tf32.f32 "
                        "{%0,%1,%2,%3}, {%4,%5,%6,%7}, {%8,%9}, {%0,%1,%2,%3};"
                        : "+f"(c[0]), "+f"(c[1]), "+f"(c[2]), "+f"(c[3])
                        : "r"(a0[0]), "r"(a0[1]), "r"(a0[2]), "r"(a0[3]),
                          "r"(b0), "r"(b1));
                }
                {
                    float* c = &acc[(8 + ni) * 4];
                    asm volatile(
                        "mma.sync.aligned.m16n8k8.row.col.f32.tf32.tf32.f32 "
                        "{%0,%1,%2,%3}, {%4,%5,%6,%7}, {%8,%9}, {%0,%1,%2,%3};"
                        : "+f"(c[0]), "+f"(c[1]), "+f"(c[2]), "+f"(c[3])
                        : "r"(a1[0]), "r"(a1[1]), "r"(a1[2]), "r"(a1[3]),
                          "r"(b0), "r"(b1));
                }
            }
    }
}

// ---------------------------------------------------------------------------
// Combined prep (one launch, flattened grid, 256 thr):
//   blocks [0, 192):    g_Vr[j][e]  = rna(V[e][j])      (32x32 tiles)
//   blocks [192, 384):  g_Bwt[j][d] = Bw[d][j]
//   blocks [384, 4480): g_Ub[b][d][e] = rna(U[d][e] * sigmoid(z[b][e]))
// ---------------------------------------------------------------------------
__global__ void prep_all(const float* __restrict__ U, const float* __restrict__ z,
                         const float* __restrict__ V, const float* __restrict__ Bw)
{
    const int bid = blockIdx.x;
    const int t   = (int)threadIdx.x;
    if (bid < 384) {
        __shared__ float tile[32][33];
        const bool isV = (bid < 192);
        const int idx  = isV ? bid : bid - 192;
        const int j0 = (idx % 24) * 32, e0 = (idx / 24) * 32;
        const int tx = t & 31, ty = t >> 5;
        const float* src = isV ? V : Bw;
        float* dst = isV ? g_Vr : g_Bwt;
        #pragma unroll
        for (int i = 0; i < 4; ++i) {
            const int r = ty + i * 8;
            float v = src[(size_t)(e0 + r) * NJ + j0 + tx];
            if (isV) v = rna(v);
            tile[r][tx] = v;
        }
        __syncthreads();
        #pragma unroll
        for (int i = 0; i < 4; ++i) {
            const int r = ty + i * 8;
            dst[(size_t)(j0 + r) * DIN + e0 + tx] = tile[tx][r];
        }
    } else {
        const int q = bid - 384;           // 4096 blocks: b = q>>6, dblk = q&63
        const int b = q >> 6, dblk = q & 63;
        const int d  = dblk * 4 + (t >> 6);
        const int e4 = (t & 63) * 4;
        const float4 u  = *(const float4*)(U + (size_t)d * DIN + e4);
        const float4 zv = *(const float4*)(z + (size_t)b * DIN + e4);
        float4 o;
        o.x = rna(u.x / (1.f + expf(-zv.x)));
        o.y = rna(u.y / (1.f + expf(-zv.y)));
        o.z = rna(u.z / (1.f + expf(-zv.z)));
        o.w = rna(u.w / (1.f + expf(-zv.w)));
        *(float4*)(g_Ub + ((size_t)(b * DIN + d)) * DIN + e4) = o;
    }
}

// ---------------------------------------------------------------------------
// GEMM1 (roles swapped): per b: D[j][d] = sum_e Vr[j][e] * Ub[b][d][e]
//   M = j (6 tiles of 128 over 768), N = d (2 tiles of 128 over 256), K=256
//   epilogue: + Bwt[j][d], rna, store g_Wt[b][f][kq*256+d]  — coalesced in d
// ---------------------------------------------------------------------------
__global__ __launch_bounds__(256, 2)
void gemm_w()
{
    extern __shared__ char sm[];
    const int b = blockIdx.z, m0 = blockIdx.x * 128, n0 = blockIdx.y * 128;
    const int kq = m0 >> 8, f0 = m0 & 255;
    const int tid = (int)threadIdx.x, wid = tid >> 5, lane = tid & 31;
    const int gid = lane >> 2, tig = lane & 3, wm = wid & 3, wn = wid >> 2;

    const uint32_t sb = smem_u32(sm);
    const float* Asrc = g_Vr + (size_t)m0 * DIN;                         // [j][e]
    const float* Bsrc = g_Ub + (size_t)b * DIN * DIN + (size_t)n0 * DIN; // [d][e]

    float acc[64];
    #pragma unroll
    for (int i = 0; i < 64; ++i) acc[i] = 0.f;

    auto load = [&](int t) {
        const int e0 = t * 32, st = t % NSTAGE;
        const uint32_t ab = sb + st * STAGE_BYTES;
        const uint32_t bb = ab + 16384;
        #pragma unroll
        for (int i = 0; i < 4; ++i) {
            const int c = tid + i * 256;
            const int r = c >> 3, c4 = c & 7;
            CP16(ab + r * 128 + ((c4 ^ (r & 7)) << 4),
                 Asrc + (size_t)r * DIN + e0 + c4 * 4);
        }
        #pragma unroll
        for (int i = 0; i < 4; ++i) {
            const int c = tid + i * 256;
            const int r = c >> 3, c4 = c & 7;
            CP16(bb + r * 128 + ((c4 ^ (r & 7)) << 4),
                 Bsrc + (size_t)r * DIN + e0 + c4 * 4);
        }
        CP_COMMIT();
    };

    load(0); load(1);
    for (int t = 0; t < 8; ++t) {
        if (t < 7) CP_WAIT1(); else CP_WAIT0();
        __syncthreads();
        if (t + 2 < 8) load(t + 2);
        const uint32_t stg = sb + (t % NSTAGE) * STAGE_BYTES;
        tile_mma(acc, stg, stg + 16384, lane, wm, wn);
    }

    // epilogue: + Bwt, rna, store g_Wt[b][f][kq*256+d] (contiguous in d)
    #pragma unroll
    for (int mi = 0; mi < 2; ++mi)
        #pragma unroll
        for (int h = 0; h < 2; ++h) {
            const int jl = wm * 32 + mi * 16 + gid + 8 * h;   // j within tile
            const int f  = f0 + jl;
            const float* BwRow = g_Bwt + (size_t)(m0 + jl) * DIN + n0;
            float* Wrow = g_Wt + (size_t)b * NF * NJ + (size_t)f * NJ
                        + (size_t)kq * DIN + n0;
            #pragma unroll
            for (int ni = 0; ni < 8; ++ni) {
                const int dl = wn * 64 + ni * 8 + 2 * tig;
                const float2 bw = *(const float2*)(BwRow + dl);
                const float* c = &acc[(mi * 8 + ni) * 4 + 2 * h];
                float2 w;
                w.x = rna(c[0] + bw.x);
                w.y = rna(c[1] + bw.y);
                *(float2*)(Wrow + dl) = w;
            }
        }
}

// ---------------------------------------------------------------------------
// Conv: per b: out[l][f] = relu( sum_{kd<768} A[l][kd] * Wt[b][f][kd] + bias )
//   A[l][kd] = x[b] flat at (l-1)*256 + kd, zero outside [0, 512*256)
//   A raw fp32 (HW truncates to tf32); W pre-rounded rna.
//   CTA 128x128, 256 thr (8 warps, 4x2 of 32x64), BK=32, K=768 (24 tiles)
// ---------------------------------------------------------------------------
__global__ __launch_bounds__(256, 2)
void conv_mma(const float* __restrict__ x,
              const float* __restrict__ bias, float* __restrict__ out)
{
    extern __shared__ char sm[];
    const int b = blockIdx.z, l0 = blockIdx.y * 128, f0 = blockIdx.x * 128;
    const int tid = (int)threadIdx.x, wid = tid >> 5, lane = tid & 31;
    const int gid = lane >> 2, tig = lane & 3, wm = wid & 3, wn = wid >> 2;

    const uint32_t sb = smem_u32(sm);
    const float* xb = x + (size_t)b * SEQL * DIN;
    const float* Wsrc = g_Wt + ((size_t)b * NF + f0) * NJ;

    float acc[64];
    #pragma unroll
    for (int i = 0; i < 64; ++i) acc[i] = 0.f;

    auto load = [&](int t) {
        const int e0 = t * 32, st = t % NSTAGE;
        const uint32_t ab = sb + st * STAGE_BYTES;
        const uint32_t bb = ab + 16384;
        #pragma unroll
        for (int i = 0; i < 4; ++i) {
            const int c = tid + i * 256;
            const int r = c >> 3, c4 = c & 7;
            const int idx = (l0 + r - 1) * DIN + e0 + c4 * 4;
            const unsigned ok = ((unsigned)idx < (unsigned)(SEQL * DIN));
            const float* src = xb + (ok ? idx : 0);
            CP16Z(ab + r * 128 + ((c4 ^ (r & 7)) << 4), src, ok ? 16u : 0u);
        }
        #pragma unroll
        for (int i = 0; i < 4; ++i) {
            const int c = tid + i * 256;
            const int r = c >> 3, c4 = c & 7;
            CP16(bb + r * 128 + ((c4 ^ (r & 7)) << 4),
                 Wsrc + (size_t)r * NJ + e0 + c4 * 4);
        }
        CP_COMMIT();
    };

    load(0); load(1);
    for (int t = 0; t < 24; ++t) {
        if (t < 23) CP_WAIT1(); else CP_WAIT0();
        __syncthreads();
        if (t + 2 < 24) load(t + 2);
        const uint32_t stg = sb + (t % NSTAGE) * STAGE_BYTES;
        tile_mma(acc, stg, stg + 16384, lane, wm, wn);
    }

    // epilogue: + bias, relu, store (f contiguous)
    #pragma unroll
    for (int mi = 0; mi < 2; ++mi)
        #pragma unroll
        for (int h = 0; h < 2; ++h) {
            const int l = l0 + wm * 32 + mi * 16 + gid + 8 * h;
            float* Orow = out + ((size_t)b * SEQL + l) * NF + f0;
            #pragma unroll
            for (int ni = 0; ni < 8; ++ni) {
                const int fl = wn * 64 + ni * 8 + 2 * tig;
                const float2 bv = *(const float2*)(bias + f0 + fl);
                const float* c = &acc[(mi * 8 + ni) * 4 + 2 * h];
                float2 o;
                o.x = fmaxf(c[0] + bv.x, 0.f);
                o.y = fmaxf(c[1] + bv.y, 0.f);
                *(float2*)(Orow + fl) = o;
            }
        }
}

// ---------------------------------------------------------------------------
// kernel_launch: prep_all -> gemm_w -> conv (capturable, no allocs)
// Inputs: x, z, U, V, B_w, b, kernel_size(ignored; KSZ=3)
// ---------------------------------------------------------------------------
extern "C" void kernel_launch(void* const* d_in, const int* in_sizes, int n_in,
                              void* d_out, int out_size)
{
    (void)in_sizes; (void)n_in; (void)out_size;
    const float* x    = (const float*)d_in[0];
    const float* z    = (const float*)d_in[1];
    const float* U    = (const float*)d_in[2];
    const float* V    = (const float*)d_in[3];
    const float* Bw   = (const float*)d_in[4];
    const float* bias = (const float*)d_in[5];
    float* out = (float*)d_out;

    static bool attr_done = false;
    if (!attr_done) {
        cudaFuncSetAttribute(gemm_w,   cudaFuncAttributeMaxDynamicSharedMemorySize, SMEM_BYTES);
        cudaFuncSetAttribute(conv_mma, cudaFuncAttributeMaxDynamicSharedMemorySize, SMEM_BYTES);
        attr_done = true;
    }

    prep_all<<<4480, 256>>>(U, z, V, Bw);
    gemm_w<<<dim3(NJ / 128, DIN / 128, NB), 256, SMEM_BYTES>>>();
    conv_mma<<<dim3(NF / 128, SEQL / 128, NB), 256, SMEM_BYTES>>>(x, bias, out);
}